// round 12
// baseline (speedup 1.0000x reference)
#include <cuda_runtime.h>
#include <math.h>

// Problem constants
#define Bc 32
#define Nc 512
#define Dc 512
#define Ec 8
#define Pc 96
#define Kc 25
#define Hc 4
#define DKc 128
#define PADc 12
#define BNc (Bc * Nc)   // 16384
#define EHc 32          // E*H

// ---------------- scratch (device globals) -----------------------------------
__device__ __align__(16) float g_qkT[Dc * EHc];            // [d][eh]
__device__ float g_qb[EHc];
__device__ __align__(16) float g_sc[(size_t)Bc * EHc * Nc];// scores/softmax [b][eh][n]
__device__ __align__(16) float g_y[(size_t)Bc * EHc * Dc]; // [b][eh][d]
__device__ __align__(16) float g_att[Bc * Ec * Dc];
__device__ __align__(16) float g_atto[Bc * Ec * Dc];
__device__ int   g_idx[BNc];
__device__ __align__(16) float g_wx[(size_t)Ec * Dc * Pc]; // [e][d][p]
__device__ float g_zlin[Bc * Ec * Pc];
__device__ int   g_blkcnt[128 * Ec];     // per 128-token block
__device__ int   g_blkoff[128 * Ec];
__device__ int   g_off[Ec + 1];
__device__ int   g_tok[BNc];

// ---------------- kA: fused q-projection + qk fold (per eh) ------------------
__global__ __launch_bounds__(256) void kA_qk(const float* __restrict__ router,
                                             const float* __restrict__ Wq,
                                             const float* __restrict__ bq,
                                             const float* __restrict__ Wk,
                                             const float* __restrict__ bk) {
    int eh = blockIdx.x;
    int e = eh >> 2, h = eh & 3;
    int tid = threadIdx.x, lane = tid & 31, warp = tid >> 5;
    __shared__ float sr[Dc];
    __shared__ float sq[DKc];
    __shared__ float red[256];

    sr[tid] = router[e * Dc + tid];
    sr[tid + 256] = router[e * Dc + 256 + tid];
    __syncthreads();

    int j = tid & 127, half = tid >> 7;
    float acc = 0.f;
    const float* wq = Wq + (size_t)(half * 256) * Dc + h * DKc + j;
    #pragma unroll 4
    for (int d = 0; d < 256; d++) acc += sr[half * 256 + d] * wq[(size_t)d * Dc];
    red[tid] = acc;
    __syncthreads();
    if (tid < DKc) sq[tid] = red[tid] + red[tid + 128] + bq[h * DKc + tid];
    __syncthreads();

    for (int d = warp; d < Dc; d += 8) {
        const float* wr = Wk + (size_t)d * Dc + h * DKc;
        float p = 0.f;
        #pragma unroll
        for (int jj = 0; jj < 4; jj++) p += wr[lane + jj * 32] * sq[lane + jj * 32];
        #pragma unroll
        for (int o = 16; o > 0; o >>= 1) p += __shfl_down_sync(0xffffffffu, p, o);
        if (lane == 0) g_qkT[d * EHc + eh] = p;
    }
    red[tid] = (tid < DKc) ? sq[tid] * bk[h * DKc + tid] : 0.f;
    __syncthreads();
    for (int s = 128; s > 0; s >>= 1) { if (tid < s) red[tid] += red[tid + s]; __syncthreads(); }
    if (tid == 0) g_qb[eh] = red[0];
}

// ---------------- k3: scores = (X @ QK + qb) * scale  (64-token blocks) ------
__global__ __launch_bounds__(128) void k3_scores(const float* __restrict__ x) {
    __shared__ float sX[32][65];     // [k][tok]  transposed
    __shared__ float sQ[32][33];     // [k][eh]
    __shared__ float sQB[EHc];
    int t0 = blockIdx.x * 64;
    int b = t0 >> 9, n0 = t0 & 511;
    int tid = threadIdx.x;
    if (tid < EHc) sQB[tid] = g_qb[tid];
    int ty = tid >> 3, tx = tid & 7;  // 16 tok-groups(4) x 8 eh-groups(4)
    float acc[4][4] = {};
    const float4* x4 = (const float4*)x;
    const float4* q4 = (const float4*)g_qkT;
    for (int kk = 0; kk < Dc; kk += 32) {
        #pragma unroll
        for (int jj = 0; jj < 4; jj++) {
            int id = tid + jj * 128;          // 512 float4
            int tok = id >> 3, c4 = id & 7;
            float4 v = x4[((size_t)(t0 + tok) * Dc + kk) / 4 + c4];
            sX[c4 * 4 + 0][tok] = v.x;
            sX[c4 * 4 + 1][tok] = v.y;
            sX[c4 * 4 + 2][tok] = v.z;
            sX[c4 * 4 + 3][tok] = v.w;
        }
        #pragma unroll
        for (int jj = 0; jj < 2; jj++) {
            int id = tid + jj * 128;          // 256 float4
            int k = id >> 3, e4 = id & 7;
            float4 v = q4[((size_t)(kk + k) * EHc) / 4 + e4];
            sQ[k][e4 * 4 + 0] = v.x;
            sQ[k][e4 * 4 + 1] = v.y;
            sQ[k][e4 * 4 + 2] = v.z;
            sQ[k][e4 * 4 + 3] = v.w;
        }
        __syncthreads();
        #pragma unroll
        for (int k = 0; k < 32; k++) {
            float q[4], a[4];
            #pragma unroll
            for (int jj = 0; jj < 4; jj++) q[jj] = sQ[k][tx * 4 + jj];
            #pragma unroll
            for (int i = 0; i < 4; i++) a[i] = sX[k][ty * 4 + i];
            #pragma unroll
            for (int i = 0; i < 4; i++)
                #pragma unroll
                for (int jj = 0; jj < 4; jj++) acc[i][jj] += a[i] * q[jj];
        }
        __syncthreads();
    }
    const float scale = 0.08838834764831845f;
    #pragma unroll
    for (int i = 0; i < 4; i++) {
        int n = n0 + ty * 4 + i;
        #pragma unroll
        for (int jj = 0; jj < 4; jj++) {
            int ee = tx * 4 + jj;
            g_sc[((size_t)b * EHc + ee) * Nc + n] = (acc[i][jj] + sQB[ee]) * scale;
        }
    }
}

// ---------------- k4: softmax over n per (b,eh) ------------------------------
__global__ __launch_bounds__(256) void k4_softmax() {
    int row = blockIdx.x;
    int tid = threadIdx.x;
    __shared__ float red[256];
    float v0 = g_sc[(size_t)row * Nc + tid];
    float v1 = g_sc[(size_t)row * Nc + 256 + tid];
    red[tid] = fmaxf(v0, v1);
    __syncthreads();
    for (int s = 128; s > 0; s >>= 1) { if (tid < s) red[tid] = fmaxf(red[tid], red[tid + s]); __syncthreads(); }
    float M = red[0];
    __syncthreads();
    float e0 = expf(v0 - M), e1 = expf(v1 - M);
    red[tid] = e0 + e1;
    __syncthreads();
    for (int s = 128; s > 0; s >>= 1) { if (tid < s) red[tid] += red[tid + s]; __syncthreads(); }
    float inv = 1.0f / red[0];
    g_sc[(size_t)row * Nc + tid] = e0 * inv;
    g_sc[(size_t)row * Nc + 256 + tid] = e1 * inv;
}

// ---------------- k5: y[b][eh][d-block64] = A @ X ----------------------------
__global__ __launch_bounds__(128) void k5_y(const float* __restrict__ x) {
    __shared__ float sA[32][33];      // [eh][n]
    __shared__ float sX[32][64];      // [n][d]
    int d0 = blockIdx.x * 64;
    int b = blockIdx.y;
    int tid = threadIdx.x;
    int ty = tid >> 4, tx = tid & 15;  // 8 eh-groups(4) x 16 d-lanes(4, stride16)
    float acc[4][4] = {};
    const float4* x4 = (const float4*)x;
    const float4* s4 = (const float4*)g_sc;
    float4* sX4 = (float4*)sX;
    for (int kk = 0; kk < Nc; kk += 32) {
        #pragma unroll
        for (int jj = 0; jj < 2; jj++) {
            int id = tid + jj * 128;           // 256 float4 (A: 32eh x 32n)
            int ee = id >> 3, n4 = id & 7;
            float4 v = s4[(((size_t)b * EHc + ee) * Nc + kk) / 4 + n4];
            sA[ee][n4 * 4 + 0] = v.x;
            sA[ee][n4 * 4 + 1] = v.y;
            sA[ee][n4 * 4 + 2] = v.z;
            sA[ee][n4 * 4 + 3] = v.w;
        }
        #pragma unroll
        for (int jj = 0; jj < 4; jj++) {
            int id = tid + jj * 128;           // 512 float4 (X: 32n x 64d)
            int n = id >> 4, d4 = id & 15;
            sX4[n * 16 + d4] = x4[(((size_t)b * Nc + kk + n) * Dc + d0) / 4 + d4];
        }
        __syncthreads();
        #pragma unroll
        for (int n = 0; n < 32; n++) {
            float xv[4], a[4];
            #pragma unroll
            for (int i = 0; i < 4; i++) xv[i] = sX[n][tx + i * 16];
            #pragma unroll
            for (int r = 0; r < 4; r++) a[r] = sA[ty * 4 + r][n];
            #pragma unroll
            for (int r = 0; r < 4; r++)
                #pragma unroll
                for (int i = 0; i < 4; i++) acc[r][i] += a[r] * xv[i];
        }
        __syncthreads();
    }
    #pragma unroll
    for (int r = 0; r < 4; r++)
        #pragma unroll
        for (int i = 0; i < 4; i++)
            g_y[((size_t)b * EHc + ty * 4 + r) * Dc + d0 + tx + i * 16] = acc[r][i];
}

// ---------------- k6: att = y @ Wv(head block) + bv --------------------------
__global__ __launch_bounds__(128) void k6_att(const float* __restrict__ Wv,
                                              const float* __restrict__ bv) {
    int c0 = blockIdx.x * 32;
    int r0 = blockIdx.y * 32;
    int h = c0 >> 7;
    __shared__ float sY[32][33];
    __shared__ float sW[32][33];
    int tid = threadIdx.x;
    int ty = tid >> 4, tx = tid & 15;
    float acc[4][2] = {};
    for (int kk = 0; kk < Dc; kk += 32) {
        #pragma unroll
        for (int jj = 0; jj < 8; jj++) {
            int id = tid + jj * 128;
            int r = id >> 5, k = id & 31;
            sY[r][k] = g_y[((size_t)(r0 + r) * 4 + h) * Dc + kk + k];
        }
        #pragma unroll
        for (int jj = 0; jj < 8; jj++) {
            int id = tid + jj * 128;
            int k = id >> 5, c = id & 31;
            sW[k][c] = Wv[(size_t)(kk + k) * Dc + c0 + c];
        }
        __syncthreads();
        #pragma unroll
        for (int k = 0; k < 32; k++) {
            float w0 = sW[k][tx], w1 = sW[k][tx + 16];
            #pragma unroll
            for (int i = 0; i < 4; i++) {
                float a = sY[ty * 4 + i][k];
                acc[i][0] += a * w0;
                acc[i][1] += a * w1;
            }
        }
        __syncthreads();
    }
    #pragma unroll
    for (int i = 0; i < 4; i++) {
        int row = r0 + ty * 4 + i;
        g_att[(size_t)row * Dc + c0 + tx]      = acc[i][0] + bv[c0 + tx];
        g_att[(size_t)row * Dc + c0 + tx + 16] = acc[i][1] + bv[c0 + tx + 16];
    }
}

// ---------------- k7: atto = att @ Wo + bo -----------------------------------
__global__ __launch_bounds__(128) void k7_oproj(const float* __restrict__ Wo,
                                                const float* __restrict__ bo) {
    int c0 = blockIdx.x * 32;
    int r0 = blockIdx.y * 32;
    __shared__ float sA[32][33];
    __shared__ float sW[32][33];
    int tid = threadIdx.x;
    int ty = tid >> 4, tx = tid & 15;
    float acc[4][2] = {};
    for (int kk = 0; kk < Dc; kk += 32) {
        #pragma unroll
        for (int jj = 0; jj < 8; jj++) {
            int id = tid + jj * 128;
            int r = id >> 5, k = id & 31;
            sA[r][k] = g_att[(size_t)(r0 + r) * Dc + kk + k];
        }
        #pragma unroll
        for (int jj = 0; jj < 8; jj++) {
            int id = tid + jj * 128;
            int k = id >> 5, c = id & 31;
            sW[k][c] = Wo[(size_t)(kk + k) * Dc + c0 + c];
        }
        __syncthreads();
        #pragma unroll
        for (int k = 0; k < 32; k++) {
            float w0 = sW[k][tx], w1 = sW[k][tx + 16];
            #pragma unroll
            for (int i = 0; i < 4; i++) {
                float a = sA[ty * 4 + i][k];
                acc[i][0] += a * w0;
                acc[i][1] += a * w1;
            }
        }
        __syncthreads();
    }
    #pragma unroll
    for (int i = 0; i < 4; i++) {
        int row = r0 + ty * 4 + i;
        g_atto[(size_t)row * Dc + c0 + tx]      = acc[i][0] + bo[c0 + tx];
        g_atto[(size_t)row * Dc + c0 + tx + 16] = acc[i][1] + bo[c0 + tx + 16];
    }
}

// ---------------- k9: routing argmax + per-block expert counts ---------------
// 128 tokens per block (halves redundant atto staging vs 64-token blocks)
__global__ __launch_bounds__(128) void k9_route(const float* __restrict__ x) {
    int b = blockIdx.y;
    int n0 = blockIdx.x * 128;
    int tid = threadIdx.x;
    __shared__ float4 s_att4[Ec][DKc];   // [e][d/4], 16KB
    __shared__ float  s_red[Ec][16];
    __shared__ float  s_norm[Ec];
    __shared__ int    s_cnt[Ec];

    const float4* a4 = (const float4*)(g_atto + (size_t)b * Ec * Dc);
    for (int i = tid; i < Ec * DKc; i += 128)
        s_att4[i >> 7][i & 127] = a4[i];
    if (tid < Ec) s_cnt[tid] = 0;
    __syncthreads();

    // norms: 16 threads per expert, 8 float4 each
    {
        int e = tid >> 4, seg = tid & 15;
        float ps = 0.f;
        #pragma unroll
        for (int q = 0; q < 8; q++) {
            float4 v = s_att4[e][seg * 8 + q];
            ps += v.x * v.x + v.y * v.y + v.z * v.z + v.w * v.w;
        }
        s_red[e][seg] = ps;
    }
    __syncthreads();
    if (tid < Ec) {
        float s = 0.f;
        #pragma unroll
        for (int q = 0; q < 16; q++) s += s_red[tid][q];
        s_norm[tid] = sqrtf(s);
    }
    __syncthreads();

    int t = b * Nc + n0 + tid;
    const float4* xr4 = (const float4*)(x + (size_t)t * Dc);
    float acc[Ec] = {};
    #pragma unroll 4
    for (int d4 = 0; d4 < DKc; d4++) {
        float4 xv = xr4[d4];
        #pragma unroll
        for (int e = 0; e < Ec; e++) {
            float4 av = s_att4[e][d4];
            acc[e] += xv.x * av.x + xv.y * av.y + xv.z * av.z + xv.w * av.w;
        }
    }
    float best = -INFINITY; int bi = 0;
    #pragma unroll
    for (int e = 0; e < Ec; e++) {
        float v = acc[e] / s_norm[e];
        if (v > best) { best = v; bi = e; }   // first-max, matches jnp.argmax
    }
    g_idx[t] = bi;
    atomicAdd(&s_cnt[bi], 1);
    __syncthreads();
    if (tid < Ec) g_blkcnt[(b * 4 + blockIdx.x) * Ec + tid] = s_cnt[tid];
}

// ---------------- kg2: warp-parallel scan of 128x8 block counts --------------
__global__ __launch_bounds__(256) void kg2_scan() {
    __shared__ int stot[Ec];
    __shared__ int soff[Ec];
    int tid = threadIdx.x, lane = tid & 31, w = tid >> 5;   // w = expert (8 warps)
    int run = 0;
    #pragma unroll
    for (int chunk = 0; chunk < 4; chunk++) {
        int i = chunk * 32 + lane;                 // 128 blocks
        int c = g_blkcnt[i * Ec + w];
        int s = c;
        #pragma unroll
        for (int o = 1; o < 32; o <<= 1) {
            int t = __shfl_up_sync(0xffffffffu, s, o);
            if (lane >= o) s += t;
        }
        g_blkoff[i * Ec + w] = run + s - c;        // exclusive prefix (pre-soff)
        run += __shfl_sync(0xffffffffu, s, 31);
    }
    if (lane == 0) stot[w] = run;
    __syncthreads();
    if (tid == 0) {
        int acc = 0;
        for (int e = 0; e < Ec; e++) { soff[e] = acc; g_off[e] = acc; acc += stot[e]; }
        g_off[Ec] = acc;
    }
    __syncthreads();
    int so = soff[w];
    #pragma unroll
    for (int chunk = 0; chunk < 4; chunk++) {
        int i = chunk * 32 + lane;
        g_blkoff[i * Ec + w] += so;
    }
}

// ---------------- kg3: scatter tokens grouped by expert ----------------------
__global__ __launch_bounds__(128) void kg3_scatter() {
    __shared__ int cnt[Ec];
    int blk = blockIdx.x, tid = threadIdx.x;
    if (tid < Ec) cnt[tid] = 0;
    __syncthreads();
    int t = blk * 128 + tid;
    int e = g_idx[t];
    int p = atomicAdd(&cnt[e], 1);
    g_tok[g_blkoff[blk * Ec + e] + p] = t;
}

// ---------------- kP1: fold conv_x into Wp -----------------------------------
__global__ __launch_bounds__(128) void kP1_fold(const float* __restrict__ Wc,
                                                const float* __restrict__ Wp) {
    int e = blockIdx.x;
    int m0 = blockIdx.y * 32;
    int tid = threadIdx.x;
    __shared__ float sWp[56][Pc];
    __shared__ float swc[Kc];
    for (int id = tid; id < 56 * Pc; id += 128) {
        int lr = id / Pc, p = id - lr * Pc;
        int l = m0 - 12 + lr;
        sWp[lr][p] = (l >= 0 && l < Dc) ? Wp[(size_t)e * Dc * Pc + (size_t)l * Pc + p] : 0.f;
    }
    if (tid < Kc) swc[tid] = Wc[e * 2 * Kc + tid];
    __syncthreads();
    if (tid < Pc) {
        #pragma unroll 2
        for (int m = 0; m < 32; m++) {
            float acc = 0.f;
            #pragma unroll
            for (int k = 0; k < Kc; k++) acc += swc[k] * sWp[m + 24 - k][tid];
            g_wx[(size_t)e * Dc * Pc + (size_t)(m0 + m) * Pc + tid] = acc;
        }
    }
}

// ---------------- kP2: z-branch per (b,e) ------------------------------------
__global__ __launch_bounds__(128) void kP2_z(const float* __restrict__ Wc,
                                             const float* __restrict__ bc,
                                             const float* __restrict__ Wp,
                                             const float* __restrict__ bp) {
    int r = blockIdx.x;      // b*8+e
    int e = r & 7;
    int tid = threadIdx.x;
    __shared__ float zp[Dc + 2 * PADc];
    __shared__ float cz[Dc];
    __shared__ float swz[Kc];
    __shared__ float s_bc;

    const float* zr = g_atto + (size_t)r * Dc;
    for (int i = tid; i < Dc + 2 * PADc; i += 128) {
        bool in = (i >= PADc) && (i < Dc + PADc);
        zp[i] = in ? zr[i - PADc] : 0.f;
    }
    if (tid < Kc) swz[tid] = Wc[e * 2 * Kc + Kc + tid];
    if (tid == 0) s_bc = bc[e];
    __syncthreads();
    #pragma unroll
    for (int jj = 0; jj < 4; jj++) {
        int l = tid * 4 + jj;
        if (l < Dc) {
            float acc = s_bc;
            #pragma unroll
            for (int k = 0; k < Kc; k++) acc += swz[k] * zp[l + k];
            cz[l] = acc;
        }
    }
    __syncthreads();
    if (tid < Pc) {
        const float* wp = Wp + (size_t)e * Dc * Pc + tid;
        float a0 = bp[e * Pc + tid], a1 = 0, a2 = 0, a3 = 0;
        for (int l = 0; l < Dc; l += 4) {
            a0 += cz[l + 0] * wp[(size_t)(l + 0) * Pc];
            a1 += cz[l + 1] * wp[(size_t)(l + 1) * Pc];
            a2 += cz[l + 2] * wp[(size_t)(l + 2) * Pc];
            a3 += cz[l + 3] * wp[(size_t)(l + 3) * Pc];
        }
        g_zlin[r * Pc + tid] = (a0 + a1) + (a2 + a3);
    }
}

// ---------------- k11: grouped GEMM  out = x @ Wxe[e] + zlin -----------------
// 64 tokens x 96 outputs per block, 128 threads, 8x6 per-thread tile.
__global__ __launch_bounds__(128) void k11_lin(const float* __restrict__ x,
                                               float* __restrict__ out) {
    int e = blockIdx.y;
    int c = blockIdx.x;
    int off0 = g_off[e], off1 = g_off[e + 1];
    int base = off0 + c * 64;
    if (base >= off1) return;

    __shared__ float sX[64][33];       // [tok][k]
    __shared__ float sW[32][98];       // [k][p], even stride for float2 loads
    __shared__ int   stok[64];
    __shared__ int   sval[64];
    int tid = threadIdx.x;
    if (tid < 64) {
        int s = base + tid;
        int v = (s < off1) ? 1 : 0;
        stok[tid] = v ? g_tok[s] : 0;
        sval[tid] = v;
    }
    __syncthreads();

    int ty = tid >> 4, tx = tid & 15;  // 8 tok-groups(8) x 16 p-lanes(6)
    float acc[8][6] = {};
    const float4* x4 = (const float4*)x;
    const float4* w4 = (const float4*)(g_wx + (size_t)e * Dc * Pc);
    for (int kk = 0; kk < Dc; kk += 32) {
        #pragma unroll
        for (int jj = 0; jj < 4; jj++) {
            int id = tid + jj * 128;
            int rr = id >> 3, k4 = id & 7;
            float4 v = sval[rr] ? x4[((size_t)stok[rr] * Dc + kk) / 4 + k4]
                                : make_float4(0.f, 0.f, 0.f, 0.f);
            sX[rr][k4 * 4 + 0] = v.x;
            sX[rr][k4 * 4 + 1] = v.y;
            sX[rr][k4 * 4 + 2] = v.z;
            sX[rr][k4 * 4 + 3] = v.w;
        }
        #pragma unroll
        for (int jj = 0; jj < 6; jj++) {
            int id = tid + jj * 128;
            int k = id / 24, p4 = id - k * 24;
            float4 v = w4[((size_t)(kk + k) * Pc) / 4 + p4];
            float* dst = &sW[k][p4 * 4];
            dst[0] = v.x; dst[1] = v.y; dst[2] = v.z; dst[3] = v.w;
        }
        __syncthreads();
        #pragma unroll
        for (int k = 0; k < 32; k++) {
            const float2* wp2 = (const float2*)&sW[k][tx * 6];
            float2 w01 = wp2[0], w23 = wp2[1], w45 = wp2[2];
            float w[6] = {w01.x, w01.y, w23.x, w23.y, w45.x, w45.y};
            #pragma unroll
            for (int i = 0; i < 8; i++) {
                float a = sX[ty * 8 + i][k];
                #pragma unroll
                for (int jj = 0; jj < 6; jj++) acc[i][jj] += a * w[jj];
            }
        }
        __syncthreads();
    }
    #pragma unroll
    for (int i = 0; i < 8; i++) {
        int rr = ty * 8 + i;
        if (sval[rr]) {
            int tt = stok[rr];
            int zb = ((tt >> 9) * Ec + e) * Pc;
            #pragma unroll
            for (int jj = 0; jj < 6; jj++)
                out[(size_t)tt * Pc + tx * 6 + jj] = acc[i][jj] + g_zlin[zb + tx * 6 + jj];
        }
    }
}

// ---------------- launcher ---------------------------------------------------
extern "C" void kernel_launch(void* const* d_in, const int* in_sizes, int n_in,
                              void* d_out, int out_size) {
    const float* x      = (const float*)d_in[0];
    const float* router = (const float*)d_in[1];
    const float* Wq     = (const float*)d_in[2];
    const float* bq     = (const float*)d_in[3];
    const float* Wk     = (const float*)d_in[4];
    const float* bk     = (const float*)d_in[5];
    const float* Wv     = (const float*)d_in[6];
    const float* bv     = (const float*)d_in[7];
    const float* Wo     = (const float*)d_in[8];
    const float* bo     = (const float*)d_in[9];
    const float* Wc     = (const float*)d_in[10];
    const float* bc     = (const float*)d_in[11];
    const float* Wp     = (const float*)d_in[12];
    const float* bp     = (const float*)d_in[13];
    float* out = (float*)d_out;

    kP1_fold<<<dim3(Ec, 16), 128>>>(Wc, Wp);
    kA_qk<<<EHc, 256>>>(router, Wq, bq, Wk, bk);
    k3_scores<<<BNc / 64, 128>>>(x);
    k4_softmax<<<Bc * EHc, 256>>>();
    k5_y<<<dim3(Dc / 64, Bc), 128>>>(x);
    k6_att<<<dim3(16, 8), 128>>>(Wv, bv);
    k7_oproj<<<dim3(16, 8), 128>>>(Wo, bo);
    k9_route<<<dim3(Nc / 128, Bc), 128>>>(x);
    kg2_scan<<<1, 256>>>();
    kg3_scatter<<<128, 128>>>();
    kP2_z<<<Bc * Ec, 128>>>(Wc, bc, Wp, bp);
    k11_lin<<<dim3(BNc / 64, Ec), 128>>>(x, out);
}

// round 15
// speedup vs baseline: 1.1531x; 1.1531x over previous
#include <cuda_runtime.h>
#include <math.h>

// Problem constants
#define Bc 32
#define Nc 512
#define Dc 512
#define Ec 8
#define Pc 96
#define Kc 25
#define Hc 4
#define DKc 128
#define PADc 12
#define BNc (Bc * Nc)   // 16384
#define EHc 32          // E*H

// ---------------- scratch (device globals) -----------------------------------
__device__ __align__(16) float g_qkT[Dc * EHc];            // [d][eh]
__device__ float g_qb[EHc];
__device__ __align__(16) float g_sc[(size_t)Bc * EHc * Nc];// scores/softmax [b][eh][n]
__device__ __align__(16) float g_y[(size_t)Bc * EHc * Dc]; // [b][eh][d]
__device__ __align__(16) float g_att[Bc * Ec * Dc];
__device__ __align__(16) float g_atto[Bc * Ec * Dc];
__device__ int   g_idx[BNc];
__device__ __align__(16) float g_wx[(size_t)Ec * Dc * Pc]; // [e][d][p]
__device__ float g_zlin[Bc * Ec * Pc];
__device__ int   g_blkcnt[256 * Ec];     // per 64-token block
__device__ int   g_blkoff[256 * Ec];
__device__ int   g_off[Ec + 1];
__device__ int   g_tok[BNc];

// ---------------- kA: fused q-projection + qk fold (per eh) ------------------
__global__ __launch_bounds__(256) void kA_qk(const float* __restrict__ router,
                                             const float* __restrict__ Wq,
                                             const float* __restrict__ bq,
                                             const float* __restrict__ Wk,
                                             const float* __restrict__ bk) {
    int eh = blockIdx.x;
    int e = eh >> 2, h = eh & 3;
    int tid = threadIdx.x, lane = tid & 31, warp = tid >> 5;
    __shared__ float sr[Dc];
    __shared__ float sq[DKc];
    __shared__ float red[256];

    sr[tid] = router[e * Dc + tid];
    sr[tid + 256] = router[e * Dc + 256 + tid];
    __syncthreads();

    int j = tid & 127, half = tid >> 7;
    float acc = 0.f;
    const float* wq = Wq + (size_t)(half * 256) * Dc + h * DKc + j;
    #pragma unroll 4
    for (int d = 0; d < 256; d++) acc += sr[half * 256 + d] * wq[(size_t)d * Dc];
    red[tid] = acc;
    __syncthreads();
    if (tid < DKc) sq[tid] = red[tid] + red[tid + 128] + bq[h * DKc + tid];
    __syncthreads();

    for (int d = warp; d < Dc; d += 8) {
        const float* wr = Wk + (size_t)d * Dc + h * DKc;
        float p = 0.f;
        #pragma unroll
        for (int jj = 0; jj < 4; jj++) p += wr[lane + jj * 32] * sq[lane + jj * 32];
        #pragma unroll
        for (int o = 16; o > 0; o >>= 1) p += __shfl_down_sync(0xffffffffu, p, o);
        if (lane == 0) g_qkT[d * EHc + eh] = p;
    }
    red[tid] = (tid < DKc) ? sq[tid] * bk[h * DKc + tid] : 0.f;
    __syncthreads();
    for (int s = 128; s > 0; s >>= 1) { if (tid < s) red[tid] += red[tid + s]; __syncthreads(); }
    if (tid == 0) g_qb[eh] = red[0];
}

// ---------------- k3: scores = (X @ QK + qb) * scale  (64-token blocks) ------
__global__ __launch_bounds__(128) void k3_scores(const float* __restrict__ x) {
    __shared__ float sX[32][65];     // [k][tok]  transposed
    __shared__ float sQ[32][33];     // [k][eh]
    __shared__ float sQB[EHc];
    int t0 = blockIdx.x * 64;
    int b = t0 >> 9, n0 = t0 & 511;
    int tid = threadIdx.x;
    if (tid < EHc) sQB[tid] = g_qb[tid];
    int ty = tid >> 3, tx = tid & 7;  // 16 tok-groups(4) x 8 eh-groups(4)
    float acc[4][4] = {};
    const float4* x4 = (const float4*)x;
    const float4* q4 = (const float4*)g_qkT;
    for (int kk = 0; kk < Dc; kk += 32) {
        #pragma unroll
        for (int jj = 0; jj < 4; jj++) {
            int id = tid + jj * 128;          // 512 float4
            int tok = id >> 3, c4 = id & 7;
            float4 v = x4[((size_t)(t0 + tok) * Dc + kk) / 4 + c4];
            sX[c4 * 4 + 0][tok] = v.x;
            sX[c4 * 4 + 1][tok] = v.y;
            sX[c4 * 4 + 2][tok] = v.z;
            sX[c4 * 4 + 3][tok] = v.w;
        }
        #pragma unroll
        for (int jj = 0; jj < 2; jj++) {
            int id = tid + jj * 128;          // 256 float4
            int k = id >> 3, e4 = id & 7;
            float4 v = q4[((size_t)(kk + k) * EHc) / 4 + e4];
            sQ[k][e4 * 4 + 0] = v.x;
            sQ[k][e4 * 4 + 1] = v.y;
            sQ[k][e4 * 4 + 2] = v.z;
            sQ[k][e4 * 4 + 3] = v.w;
        }
        __syncthreads();
        #pragma unroll
        for (int k = 0; k < 32; k++) {
            float q[4], a[4];
            #pragma unroll
            for (int jj = 0; jj < 4; jj++) q[jj] = sQ[k][tx * 4 + jj];
            #pragma unroll
            for (int i = 0; i < 4; i++) a[i] = sX[k][ty * 4 + i];
            #pragma unroll
            for (int i = 0; i < 4; i++)
                #pragma unroll
                for (int jj = 0; jj < 4; jj++) acc[i][jj] += a[i] * q[jj];
        }
        __syncthreads();
    }
    const float scale = 0.08838834764831845f;
    #pragma unroll
    for (int i = 0; i < 4; i++) {
        int n = n0 + ty * 4 + i;
        #pragma unroll
        for (int jj = 0; jj < 4; jj++) {
            int ee = tx * 4 + jj;
            g_sc[((size_t)b * EHc + ee) * Nc + n] = (acc[i][jj] + sQB[ee]) * scale;
        }
    }
}

// ---------------- k4: softmax over n per (b,eh) ------------------------------
__global__ __launch_bounds__(256) void k4_softmax() {
    int row = blockIdx.x;
    int tid = threadIdx.x;
    __shared__ float red[256];
    float v0 = g_sc[(size_t)row * Nc + tid];
    float v1 = g_sc[(size_t)row * Nc + 256 + tid];
    red[tid] = fmaxf(v0, v1);
    __syncthreads();
    for (int s = 128; s > 0; s >>= 1) { if (tid < s) red[tid] = fmaxf(red[tid], red[tid + s]); __syncthreads(); }
    float M = red[0];
    __syncthreads();
    float e0 = expf(v0 - M), e1 = expf(v1 - M);
    red[tid] = e0 + e1;
    __syncthreads();
    for (int s = 128; s > 0; s >>= 1) { if (tid < s) red[tid] += red[tid + s]; __syncthreads(); }
    float inv = 1.0f / red[0];
    g_sc[(size_t)row * Nc + tid] = e0 * inv;
    g_sc[(size_t)row * Nc + 256 + tid] = e1 * inv;
}

// ---------------- k5: y[b][eh][d-block64] = A @ X ----------------------------
__global__ __launch_bounds__(128) void k5_y(const float* __restrict__ x) {
    __shared__ float sA[32][33];      // [eh][n]
    __shared__ float sX[32][64];      // [n][d]
    int d0 = blockIdx.x * 64;
    int b = blockIdx.y;
    int tid = threadIdx.x;
    int ty = tid >> 4, tx = tid & 15;  // 8 eh-groups(4) x 16 d-lanes(4, stride16)
    float acc[4][4] = {};
    const float4* x4 = (const float4*)x;
    const float4* s4 = (const float4*)g_sc;
    float4* sX4 = (float4*)sX;
    for (int kk = 0; kk < Nc; kk += 32) {
        #pragma unroll
        for (int jj = 0; jj < 2; jj++) {
            int id = tid + jj * 128;           // 256 float4 (A: 32eh x 32n)
            int ee = id >> 3, n4 = id & 7;
            float4 v = s4[(((size_t)b * EHc + ee) * Nc + kk) / 4 + n4];
            sA[ee][n4 * 4 + 0] = v.x;
            sA[ee][n4 * 4 + 1] = v.y;
            sA[ee][n4 * 4 + 2] = v.z;
            sA[ee][n4 * 4 + 3] = v.w;
        }
        #pragma unroll
        for (int jj = 0; jj < 4; jj++) {
            int id = tid + jj * 128;           // 512 float4 (X: 32n x 64d)
            int n = id >> 4, d4 = id & 15;
            sX4[n * 16 + d4] = x4[(((size_t)b * Nc + kk + n) * Dc + d0) / 4 + d4];
        }
        __syncthreads();
        #pragma unroll
        for (int n = 0; n < 32; n++) {
            float xv[4], a[4];
            #pragma unroll
            for (int i = 0; i < 4; i++) xv[i] = sX[n][tx + i * 16];
            #pragma unroll
            for (int r = 0; r < 4; r++) a[r] = sA[ty * 4 + r][n];
            #pragma unroll
            for (int r = 0; r < 4; r++)
                #pragma unroll
                for (int i = 0; i < 4; i++) acc[r][i] += a[r] * xv[i];
        }
        __syncthreads();
    }
    #pragma unroll
    for (int r = 0; r < 4; r++)
        #pragma unroll
        for (int i = 0; i < 4; i++)
            g_y[((size_t)b * EHc + ty * 4 + r) * Dc + d0 + tx + i * 16] = acc[r][i];
}

// ---------------- k6: att = y @ Wv(head block) + bv --------------------------
__global__ __launch_bounds__(128) void k6_att(const float* __restrict__ Wv,
                                              const float* __restrict__ bv) {
    int c0 = blockIdx.x * 32;
    int r0 = blockIdx.y * 32;
    int h = c0 >> 7;
    __shared__ float sY[32][33];
    __shared__ float sW[32][33];
    int tid = threadIdx.x;
    int ty = tid >> 4, tx = tid & 15;
    float acc[4][2] = {};
    for (int kk = 0; kk < Dc; kk += 32) {
        #pragma unroll
        for (int jj = 0; jj < 8; jj++) {
            int id = tid + jj * 128;
            int r = id >> 5, k = id & 31;
            sY[r][k] = g_y[((size_t)(r0 + r) * 4 + h) * Dc + kk + k];
        }
        #pragma unroll
        for (int jj = 0; jj < 8; jj++) {
            int id = tid + jj * 128;
            int k = id >> 5, c = id & 31;
            sW[k][c] = Wv[(size_t)(kk + k) * Dc + c0 + c];
        }
        __syncthreads();
        #pragma unroll
        for (int k = 0; k < 32; k++) {
            float w0 = sW[k][tx], w1 = sW[k][tx + 16];
            #pragma unroll
            for (int i = 0; i < 4; i++) {
                float a = sY[ty * 4 + i][k];
                acc[i][0] += a * w0;
                acc[i][1] += a * w1;
            }
        }
        __syncthreads();
    }
    #pragma unroll
    for (int i = 0; i < 4; i++) {
        int row = r0 + ty * 4 + i;
        g_att[(size_t)row * Dc + c0 + tx]      = acc[i][0] + bv[c0 + tx];
        g_att[(size_t)row * Dc + c0 + tx + 16] = acc[i][1] + bv[c0 + tx + 16];
    }
}

// ---------------- k7: atto = att @ Wo + bo -----------------------------------
__global__ __launch_bounds__(128) void k7_oproj(const float* __restrict__ Wo,
                                                const float* __restrict__ bo) {
    int c0 = blockIdx.x * 32;
    int r0 = blockIdx.y * 32;
    __shared__ float sA[32][33];
    __shared__ float sW[32][33];
    int tid = threadIdx.x;
    int ty = tid >> 4, tx = tid & 15;
    float acc[4][2] = {};
    for (int kk = 0; kk < Dc; kk += 32) {
        #pragma unroll
        for (int jj = 0; jj < 8; jj++) {
            int id = tid + jj * 128;
            int r = id >> 5, k = id & 31;
            sA[r][k] = g_att[(size_t)(r0 + r) * Dc + kk + k];
        }
        #pragma unroll
        for (int jj = 0; jj < 8; jj++) {
            int id = tid + jj * 128;
            int k = id >> 5, c = id & 31;
            sW[k][c] = Wo[(size_t)(kk + k) * Dc + c0 + c];
        }
        __syncthreads();
        #pragma unroll
        for (int k = 0; k < 32; k++) {
            float w0 = sW[k][tx], w1 = sW[k][tx + 16];
            #pragma unroll
            for (int i = 0; i < 4; i++) {
                float a = sA[ty * 4 + i][k];
                acc[i][0] += a * w0;
                acc[i][1] += a * w1;
            }
        }
        __syncthreads();
    }
    #pragma unroll
    for (int i = 0; i < 4; i++) {
        int row = r0 + ty * 4 + i;
        g_atto[(size_t)row * Dc + c0 + tx]      = acc[i][0] + bo[c0 + tx];
        g_atto[(size_t)row * Dc + c0 + tx + 16] = acc[i][1] + bo[c0 + tx + 16];
    }
}

// ---------------- k9: routing argmax + per-block expert counts ---------------
__global__ __launch_bounds__(64) void k9_route(const float* __restrict__ x) {
    int b = blockIdx.y;
    int n0 = blockIdx.x * 64;
    int tid = threadIdx.x;
    __shared__ float4 s_att4[Ec][DKc];   // [e][d/4], 16KB
    __shared__ float  s_red[Ec][8];
    __shared__ float  s_norm[Ec];
    __shared__ int    s_cnt[Ec];

    const float4* a4 = (const float4*)(g_atto + (size_t)b * Ec * Dc);
    for (int i = tid; i < Ec * DKc; i += 64)
        s_att4[i >> 7][i & 127] = a4[i];
    if (tid < Ec) s_cnt[tid] = 0;
    __syncthreads();

    {
        int e = tid >> 3, seg = tid & 7;
        float ps = 0.f;
        #pragma unroll
        for (int q = 0; q < 16; q++) {
            float4 v = s_att4[e][seg * 16 + q];
            ps += v.x * v.x + v.y * v.y + v.z * v.z + v.w * v.w;
        }
        s_red[e][seg] = ps;
    }
    __syncthreads();
    if (tid < Ec) {
        float s = 0.f;
        #pragma unroll
        for (int q = 0; q < 8; q++) s += s_red[tid][q];
        s_norm[tid] = sqrtf(s);
    }
    __syncthreads();

    int t = b * Nc + n0 + tid;
    const float4* xr4 = (const float4*)(x + (size_t)t * Dc);
    float acc[Ec] = {};
    #pragma unroll 4
    for (int d4 = 0; d4 < DKc; d4++) {
        float4 xv = xr4[d4];
        #pragma unroll
        for (int e = 0; e < Ec; e++) {
            float4 av = s_att4[e][d4];
            acc[e] += xv.x * av.x + xv.y * av.y + xv.z * av.z + xv.w * av.w;
        }
    }
    float best = -INFINITY; int bi = 0;
    #pragma unroll
    for (int e = 0; e < Ec; e++) {
        float v = acc[e] / s_norm[e];
        if (v > best) { best = v; bi = e; }   // first-max, matches jnp.argmax
    }
    g_idx[t] = bi;
    atomicAdd(&s_cnt[bi], 1);
    __syncthreads();
    if (tid < Ec) g_blkcnt[(b * 8 + blockIdx.x) * Ec + tid] = s_cnt[tid];
}

// ---------------- kg2: scan 256x8 block counts -> offsets --------------------
__global__ __launch_bounds__(256) void kg2_scan() {
    __shared__ int s_cnt[256 * Ec];
    __shared__ int stot[Ec];
    __shared__ int soff[Ec];
    int tid = threadIdx.x;
    #pragma unroll
    for (int e = 0; e < Ec; e++) s_cnt[tid * Ec + e] = g_blkcnt[tid * Ec + e];
    __syncthreads();
    if (tid < Ec) {
        int run = 0;
        for (int blk = 0; blk < 256; blk++) {
            g_blkoff[blk * Ec + tid] = run;
            run += s_cnt[blk * Ec + tid];
        }
        stot[tid] = run;
    }
    __syncthreads();
    if (tid == 0) {
        int acc = 0;
        for (int e = 0; e < Ec; e++) { soff[e] = acc; g_off[e] = acc; acc += stot[e]; }
        g_off[Ec] = acc;
    }
    __syncthreads();
    #pragma unroll
    for (int e = 0; e < Ec; e++) g_blkoff[tid * Ec + e] += soff[e];
}

// ---------------- kg3: scatter tokens grouped by expert ----------------------
__global__ __launch_bounds__(64) void kg3_scatter() {
    __shared__ int cnt[Ec];
    int blk = blockIdx.x, tid = threadIdx.x;
    if (tid < Ec) cnt[tid] = 0;
    __syncthreads();
    int t = blk * 64 + tid;
    int e = g_idx[t];
    int p = atomicAdd(&cnt[e], 1);
    g_tok[g_blkoff[blk * Ec + e] + p] = t;
}

// ---------------- kP1: fold conv_x into Wp -----------------------------------
__global__ __launch_bounds__(128) void kP1_fold(const float* __restrict__ Wc,
                                                const float* __restrict__ Wp) {
    int e = blockIdx.x;
    int m0 = blockIdx.y * 32;
    int tid = threadIdx.x;
    __shared__ float sWp[56][Pc];
    __shared__ float swc[Kc];
    for (int id = tid; id < 56 * Pc; id += 128) {
        int lr = id / Pc, p = id - lr * Pc;
        int l = m0 - 12 + lr;
        sWp[lr][p] = (l >= 0 && l < Dc) ? Wp[(size_t)e * Dc * Pc + (size_t)l * Pc + p] : 0.f;
    }
    if (tid < Kc) swc[tid] = Wc[e * 2 * Kc + tid];
    __syncthreads();
    if (tid < Pc) {
        #pragma unroll 2
        for (int m = 0; m < 32; m++) {
            float acc = 0.f;
            #pragma unroll
            for (int k = 0; k < Kc; k++) acc += swc[k] * sWp[m + 24 - k][tid];
            g_wx[(size_t)e * Dc * Pc + (size_t)(m0 + m) * Pc + tid] = acc;
        }
    }
}

// ---------------- kP2: z-branch per (b,e) ------------------------------------
__global__ __launch_bounds__(128) void kP2_z(const float* __restrict__ Wc,
                                             const float* __restrict__ bc,
                                             const float* __restrict__ Wp,
                                             const float* __restrict__ bp) {
    int r = blockIdx.x;      // b*8+e
    int e = r & 7;
    int tid = threadIdx.x;
    __shared__ float zp[Dc + 2 * PADc];
    __shared__ float cz[Dc];
    __shared__ float swz[Kc];
    __shared__ float s_bc;

    const float* zr = g_atto + (size_t)r * Dc;
    for (int i = tid; i < Dc + 2 * PADc; i += 128) {
        bool in = (i >= PADc) && (i < Dc + PADc);
        zp[i] = in ? zr[i - PADc] : 0.f;
    }
    if (tid < Kc) swz[tid] = Wc[e * 2 * Kc + Kc + tid];
    if (tid == 0) s_bc = bc[e];
    __syncthreads();
    #pragma unroll
    for (int jj = 0; jj < 4; jj++) {
        int l = tid * 4 + jj;
        if (l < Dc) {
            float acc = s_bc;
            #pragma unroll
            for (int k = 0; k < Kc; k++) acc += swz[k] * zp[l + k];
            cz[l] = acc;
        }
    }
    __syncthreads();
    if (tid < Pc) {
        const float* wp = Wp + (size_t)e * Dc * Pc + tid;
        float a0 = bp[e * Pc + tid], a1 = 0, a2 = 0, a3 = 0;
        for (int l = 0; l < Dc; l += 4) {
            a0 += cz[l + 0] * wp[(size_t)(l + 0) * Pc];
            a1 += cz[l + 1] * wp[(size_t)(l + 1) * Pc];
            a2 += cz[l + 2] * wp[(size_t)(l + 2) * Pc];
            a3 += cz[l + 3] * wp[(size_t)(l + 3) * Pc];
        }
        g_zlin[r * Pc + tid] = (a0 + a1) + (a2 + a3);
    }
}

// ---------------- k11: grouped GEMM  out = x @ Wxe[e] + zlin -----------------
// Champion version: 64 tokens x 96 outputs per block, 256 threads, 4x6 tile.
__global__ __launch_bounds__(256) void k11_lin(const float* __restrict__ x,
                                               float* __restrict__ out) {
    int e = blockIdx.y;
    int c = blockIdx.x;
    int off0 = g_off[e], off1 = g_off[e + 1];
    int base = off0 + c * 64;
    if (base >= off1) return;

    __shared__ float sX[64][33];     // [tok][k]
    __shared__ float sW[32][97];     // [k][p]
    __shared__ int   stok[64];
    __shared__ int   sval[64];
    int tid = threadIdx.x;
    if (tid < 64) {
        int s = base + tid;
        int v = (s < off1) ? 1 : 0;
        stok[tid] = v ? g_tok[s] : 0;
        sval[tid] = v;
    }
    __syncthreads();

    int ty = tid >> 4, tx = tid & 15;  // 16 tok-groups(4) x 16 p-lanes(6)
    float acc[4][6] = {};
    const float4* x4 = (const float4*)x;
    const float4* w4 = (const float4*)(g_wx + (size_t)e * Dc * Pc);
    for (int kk = 0; kk < Dc; kk += 32) {
        // x tile: 64 tok x 32 k (512 float4 / 256 thr = 2)
        #pragma unroll
        for (int jj = 0; jj < 2; jj++) {
            int id = tid + jj * 256;
            int rr = id >> 3, k4 = id & 7;
            float4 v = sval[rr] ? x4[((size_t)stok[rr] * Dc + kk) / 4 + k4]
                                : make_float4(0.f, 0.f, 0.f, 0.f);
            sX[rr][k4 * 4 + 0] = v.x;
            sX[rr][k4 * 4 + 1] = v.y;
            sX[rr][k4 * 4 + 2] = v.z;
            sX[rr][k4 * 4 + 3] = v.w;
        }
        // W tile: 32 k x 96 p (768 float4 / 256 thr = 3)
        #pragma unroll
        for (int jj = 0; jj < 3; jj++) {
            int id = tid + jj * 256;
            int k = id / 24, p4 = id - k * 24;
            float4 v = w4[((size_t)(kk + k) * Pc) / 4 + p4];
            sW[k][p4 * 4 + 0] = v.x;
            sW[k][p4 * 4 + 1] = v.y;
            sW[k][p4 * 4 + 2] = v.z;
            sW[k][p4 * 4 + 3] = v.w;
        }
        __syncthreads();
        #pragma unroll
        for (int k = 0; k < 32; k++) {
            float w[6], a[4];
            #pragma unroll
            for (int jj = 0; jj < 6; jj++) w[jj] = sW[k][tx * 6 + jj];
            #pragma unroll
            for (int i = 0; i < 4; i++) a[i] = sX[ty * 4 + i][k];
            #pragma unroll
            for (int i = 0; i < 4; i++)
                #pragma unroll
                for (int jj = 0; jj < 6; jj++) acc[i][jj] += a[i] * w[jj];
        }
        __syncthreads();
    }
    #pragma unroll
    for (int i = 0; i < 4; i++) {
        int rr = ty * 4 + i;
        if (sval[rr]) {
            int tt = stok[rr];
            int zb = ((tt >> 9) * Ec + e) * Pc;
            #pragma unroll
            for (int jj = 0; jj < 6; jj++)
                out[(size_t)tt * Pc + tx * 6 + jj] = acc[i][jj] + g_zlin[zb + tx * 6 + jj];
        }
    }
}

// ---------------- launcher with stream-fork concurrency ----------------------
static cudaStream_t s_side = 0;
static cudaEvent_t  s_evRoot = 0, s_evP1 = 0, s_evAtto = 0, s_evP2 = 0;
static int s_init = 0;

extern "C" void kernel_launch(void* const* d_in, const int* in_sizes, int n_in,
                              void* d_out, int out_size) {
    const float* x      = (const float*)d_in[0];
    const float* router = (const float*)d_in[1];
    const float* Wq     = (const float*)d_in[2];
    const float* bq     = (const float*)d_in[3];
    const float* Wk     = (const float*)d_in[4];
    const float* bk     = (const float*)d_in[5];
    const float* Wv     = (const float*)d_in[6];
    const float* bv     = (const float*)d_in[7];
    const float* Wo     = (const float*)d_in[8];
    const float* bo     = (const float*)d_in[9];
    const float* Wc     = (const float*)d_in[10];
    const float* bc     = (const float*)d_in[11];
    const float* Wp     = (const float*)d_in[12];
    const float* bp     = (const float*)d_in[13];
    float* out = (float*)d_out;

    if (!s_init) {   // host-resource init only; the launched work is identical every call
        cudaStreamCreateWithFlags(&s_side, cudaStreamNonBlocking);
        cudaEventCreateWithFlags(&s_evRoot, cudaEventDisableTiming);
        cudaEventCreateWithFlags(&s_evP1,   cudaEventDisableTiming);
        cudaEventCreateWithFlags(&s_evAtto, cudaEventDisableTiming);
        cudaEventCreateWithFlags(&s_evP2,   cudaEventDisableTiming);
        s_init = 1;
    }

    // Fork side stream from main (capture-legal: event edge)
    cudaEventRecord(s_evRoot, 0);
    cudaStreamWaitEvent(s_side, s_evRoot, 0);

    // Side stream: weight fold (no deps on attention chain)
    kP1_fold<<<dim3(Ec, 16), 128, 0, s_side>>>(Wc, Wp);
    cudaEventRecord(s_evP1, s_side);

    // Main chain
    kA_qk<<<EHc, 256>>>(router, Wq, bq, Wk, bk);
    k3_scores<<<BNc / 64, 128>>>(x);
    k4_softmax<<<Bc * EHc, 256>>>();
    k5_y<<<dim3(Dc / 64, Bc), 128>>>(x);
    k6_att<<<dim3(16, 8), 128>>>(Wv, bv);
    k7_oproj<<<dim3(16, 8), 128>>>(Wo, bo);

    // atto ready: side stream runs z-branch while main does routing
    cudaEventRecord(s_evAtto, 0);
    cudaStreamWaitEvent(s_side, s_evAtto, 0);
    kP2_z<<<Bc * Ec, 128, 0, s_side>>>(Wc, bc, Wp, bp);
    cudaEventRecord(s_evP2, s_side);

    k9_route<<<dim3(Nc / 64, Bc), 64>>>(x);
    kg2_scan<<<1, 256>>>();
    kg3_scatter<<<256, 64>>>();

    // Join: k11 needs kP1 (g_wx), kP2 (g_zlin), kg3 (g_tok/g_off)
    cudaStreamWaitEvent(0, s_evP1, 0);
    cudaStreamWaitEvent(0, s_evP2, 0);
    k11_lin<<<dim3(BNc / 64, Ec), 256>>>(x, out);
}

// round 16
// speedup vs baseline: 1.1742x; 1.0183x over previous
#include <cuda_runtime.h>
#include <math.h>

// Problem constants
#define Bc 32
#define Nc 512
#define Dc 512
#define Ec 8
#define Pc 96
#define Kc 25
#define Hc 4
#define DKc 128
#define PADc 12
#define BNc (Bc * Nc)   // 16384
#define EHc 32          // E*H

// ---------------- scratch (device globals) -----------------------------------
__device__ __align__(16) float g_qkT[Dc * EHc];            // [d][eh]
__device__ float g_qb[EHc];
__device__ __align__(16) float g_sc[(size_t)Bc * EHc * Nc];// scores/softmax [b][eh][n]
__device__ __align__(16) float g_y[(size_t)Bc * EHc * Dc]; // [b][eh][d]
__device__ __align__(16) float g_att[Bc * Ec * Dc];
__device__ __align__(16) float g_atto[Bc * Ec * Dc];
__device__ int   g_idx[BNc];
__device__ __align__(16) float g_wx[(size_t)Ec * Dc * Pc]; // [e][d][p]
__device__ float g_zlin[Bc * Ec * Pc];
__device__ int   g_blkcnt[256 * Ec];     // per 64-token block
__device__ int   g_off[Ec + 1];
__device__ int   g_tok[BNc];

// ---------------- kA: fused q-projection + qk fold (per eh) ------------------
__global__ __launch_bounds__(256) void kA_qk(const float* __restrict__ router,
                                             const float* __restrict__ Wq,
                                             const float* __restrict__ bq,
                                             const float* __restrict__ Wk,
                                             const float* __restrict__ bk) {
    int eh = blockIdx.x;
    int e = eh >> 2, h = eh & 3;
    int tid = threadIdx.x, lane = tid & 31, warp = tid >> 5;
    __shared__ float sr[Dc];
    __shared__ float sq[DKc];
    __shared__ float red[256];

    sr[tid] = router[e * Dc + tid];
    sr[tid + 256] = router[e * Dc + 256 + tid];
    __syncthreads();

    int j = tid & 127, half = tid >> 7;
    float acc = 0.f;
    const float* wq = Wq + (size_t)(half * 256) * Dc + h * DKc + j;
    #pragma unroll 4
    for (int d = 0; d < 256; d++) acc += sr[half * 256 + d] * wq[(size_t)d * Dc];
    red[tid] = acc;
    __syncthreads();
    if (tid < DKc) sq[tid] = red[tid] + red[tid + 128] + bq[h * DKc + tid];
    __syncthreads();

    for (int d = warp; d < Dc; d += 8) {
        const float* wr = Wk + (size_t)d * Dc + h * DKc;
        float p = 0.f;
        #pragma unroll
        for (int jj = 0; jj < 4; jj++) p += wr[lane + jj * 32] * sq[lane + jj * 32];
        #pragma unroll
        for (int o = 16; o > 0; o >>= 1) p += __shfl_down_sync(0xffffffffu, p, o);
        if (lane == 0) g_qkT[d * EHc + eh] = p;
    }
    red[tid] = (tid < DKc) ? sq[tid] * bk[h * DKc + tid] : 0.f;
    __syncthreads();
    for (int s = 128; s > 0; s >>= 1) { if (tid < s) red[tid] += red[tid + s]; __syncthreads(); }
    if (tid == 0) g_qb[eh] = red[0];
}

// ---------------- k3: scores = (X @ QK + qb) * scale  (64-token blocks) ------
__global__ __launch_bounds__(128) void k3_scores(const float* __restrict__ x) {
    __shared__ float sX[32][65];     // [k][tok]  transposed
    __shared__ float sQ[32][33];     // [k][eh]
    __shared__ float sQB[EHc];
    int t0 = blockIdx.x * 64;
    int b = t0 >> 9, n0 = t0 & 511;
    int tid = threadIdx.x;
    if (tid < EHc) sQB[tid] = g_qb[tid];
    int ty = tid >> 3, tx = tid & 7;  // 16 tok-groups(4) x 8 eh-groups(4)
    float acc[4][4] = {};
    const float4* x4 = (const float4*)x;
    const float4* q4 = (const float4*)g_qkT;
    for (int kk = 0; kk < Dc; kk += 32) {
        #pragma unroll
        for (int jj = 0; jj < 4; jj++) {
            int id = tid + jj * 128;          // 512 float4
            int tok = id >> 3, c4 = id & 7;
            float4 v = x4[((size_t)(t0 + tok) * Dc + kk) / 4 + c4];
            sX[c4 * 4 + 0][tok] = v.x;
            sX[c4 * 4 + 1][tok] = v.y;
            sX[c4 * 4 + 2][tok] = v.z;
            sX[c4 * 4 + 3][tok] = v.w;
        }
        #pragma unroll
        for (int jj = 0; jj < 2; jj++) {
            int id = tid + jj * 128;          // 256 float4
            int k = id >> 3, e4 = id & 7;
            float4 v = q4[((size_t)(kk + k) * EHc) / 4 + e4];
            sQ[k][e4 * 4 + 0] = v.x;
            sQ[k][e4 * 4 + 1] = v.y;
            sQ[k][e4 * 4 + 2] = v.z;
            sQ[k][e4 * 4 + 3] = v.w;
        }
        __syncthreads();
        #pragma unroll
        for (int k = 0; k < 32; k++) {
            float q[4], a[4];
            #pragma unroll
            for (int jj = 0; jj < 4; jj++) q[jj] = sQ[k][tx * 4 + jj];
            #pragma unroll
            for (int i = 0; i < 4; i++) a[i] = sX[k][ty * 4 + i];
            #pragma unroll
            for (int i = 0; i < 4; i++)
                #pragma unroll
                for (int jj = 0; jj < 4; jj++) acc[i][jj] += a[i] * q[jj];
        }
        __syncthreads();
    }
    const float scale = 0.08838834764831845f;
    #pragma unroll
    for (int i = 0; i < 4; i++) {
        int n = n0 + ty * 4 + i;
        #pragma unroll
        for (int jj = 0; jj < 4; jj++) {
            int ee = tx * 4 + jj;
            g_sc[((size_t)b * EHc + ee) * Nc + n] = (acc[i][jj] + sQB[ee]) * scale;
        }
    }
}

// ---------------- k4: softmax over n per (b,eh) — float4 + shfl --------------
__global__ __launch_bounds__(128) void k4_softmax() {
    int row = blockIdx.x;
    int tid = threadIdx.x, lane = tid & 31, w = tid >> 5;
    __shared__ float sredM[4];
    __shared__ float sredS[4];
    float4* p4 = (float4*)(g_sc + (size_t)row * Nc);
    float4 v = p4[tid];                      // 128 float4 = 512 floats
    // max
    float m = fmaxf(fmaxf(v.x, v.y), fmaxf(v.z, v.w));
    #pragma unroll
    for (int o = 16; o > 0; o >>= 1) m = fmaxf(m, __shfl_xor_sync(0xffffffffu, m, o));
    if (lane == 0) sredM[w] = m;
    __syncthreads();
    float M = fmaxf(fmaxf(sredM[0], sredM[1]), fmaxf(sredM[2], sredM[3]));
    // exp + sum
    float e0 = expf(v.x - M), e1 = expf(v.y - M), e2 = expf(v.z - M), e3 = expf(v.w - M);
    float s = (e0 + e1) + (e2 + e3);
    #pragma unroll
    for (int o = 16; o > 0; o >>= 1) s += __shfl_xor_sync(0xffffffffu, s, o);
    if (lane == 0) sredS[w] = s;
    __syncthreads();
    float inv = 1.0f / ((sredS[0] + sredS[1]) + (sredS[2] + sredS[3]));
    p4[tid] = make_float4(e0 * inv, e1 * inv, e2 * inv, e3 * inv);
}

// ---------------- k5: y[b][eh][d-block64] = A @ X ----------------------------
__global__ __launch_bounds__(128) void k5_y(const float* __restrict__ x) {
    __shared__ float sA[32][33];      // [eh][n]
    __shared__ float sX[32][64];      // [n][d]
    int d0 = blockIdx.x * 64;
    int b = blockIdx.y;
    int tid = threadIdx.x;
    int ty = tid >> 4, tx = tid & 15;  // 8 eh-groups(4) x 16 d-lanes(4, stride16)
    float acc[4][4] = {};
    const float4* x4 = (const float4*)x;
    const float4* s4 = (const float4*)g_sc;
    float4* sX4 = (float4*)sX;
    for (int kk = 0; kk < Nc; kk += 32) {
        #pragma unroll
        for (int jj = 0; jj < 2; jj++) {
            int id = tid + jj * 128;           // 256 float4 (A: 32eh x 32n)
            int ee = id >> 3, n4 = id & 7;
            float4 v = s4[(((size_t)b * EHc + ee) * Nc + kk) / 4 + n4];
            sA[ee][n4 * 4 + 0] = v.x;
            sA[ee][n4 * 4 + 1] = v.y;
            sA[ee][n4 * 4 + 2] = v.z;
            sA[ee][n4 * 4 + 3] = v.w;
        }
        #pragma unroll
        for (int jj = 0; jj < 4; jj++) {
            int id = tid + jj * 128;           // 512 float4 (X: 32n x 64d)
            int n = id >> 4, d4 = id & 15;
            sX4[n * 16 + d4] = x4[(((size_t)b * Nc + kk + n) * Dc + d0) / 4 + d4];
        }
        __syncthreads();
        #pragma unroll
        for (int n = 0; n < 32; n++) {
            float xv[4], a[4];
            #pragma unroll
            for (int i = 0; i < 4; i++) xv[i] = sX[n][tx + i * 16];
            #pragma unroll
            for (int r = 0; r < 4; r++) a[r] = sA[ty * 4 + r][n];
            #pragma unroll
            for (int r = 0; r < 4; r++)
                #pragma unroll
                for (int i = 0; i < 4; i++) acc[r][i] += a[r] * xv[i];
        }
        __syncthreads();
    }
    #pragma unroll
    for (int r = 0; r < 4; r++)
        #pragma unroll
        for (int i = 0; i < 4; i++)
            g_y[((size_t)b * EHc + ty * 4 + r) * Dc + d0 + tx + i * 16] = acc[r][i];
}

// ---------------- k6: att = y @ Wv(head block) + bv --------------------------
__global__ __launch_bounds__(128) void k6_att(const float* __restrict__ Wv,
                                              const float* __restrict__ bv) {
    int c0 = blockIdx.x * 32;
    int r0 = blockIdx.y * 32;
    int h = c0 >> 7;
    __shared__ float sY[32][33];
    __shared__ float sW[32][33];
    int tid = threadIdx.x;
    int ty = tid >> 4, tx = tid & 15;
    float acc[4][2] = {};
    for (int kk = 0; kk < Dc; kk += 32) {
        #pragma unroll
        for (int jj = 0; jj < 8; jj++) {
            int id = tid + jj * 128;
            int r = id >> 5, k = id & 31;
            sY[r][k] = g_y[((size_t)(r0 + r) * 4 + h) * Dc + kk + k];
        }
        #pragma unroll
        for (int jj = 0; jj < 8; jj++) {
            int id = tid + jj * 128;
            int k = id >> 5, c = id & 31;
            sW[k][c] = Wv[(size_t)(kk + k) * Dc + c0 + c];
        }
        __syncthreads();
        #pragma unroll
        for (int k = 0; k < 32; k++) {
            float w0 = sW[k][tx], w1 = sW[k][tx + 16];
            #pragma unroll
            for (int i = 0; i < 4; i++) {
                float a = sY[ty * 4 + i][k];
                acc[i][0] += a * w0;
                acc[i][1] += a * w1;
            }
        }
        __syncthreads();
    }
    #pragma unroll
    for (int i = 0; i < 4; i++) {
        int row = r0 + ty * 4 + i;
        g_att[(size_t)row * Dc + c0 + tx]      = acc[i][0] + bv[c0 + tx];
        g_att[(size_t)row * Dc + c0 + tx + 16] = acc[i][1] + bv[c0 + tx + 16];
    }
}

// ---------------- k7: atto = att @ Wo + bo -----------------------------------
__global__ __launch_bounds__(128) void k7_oproj(const float* __restrict__ Wo,
                                                const float* __restrict__ bo) {
    int c0 = blockIdx.x * 32;
    int r0 = blockIdx.y * 32;
    __shared__ float sA[32][33];
    __shared__ float sW[32][33];
    int tid = threadIdx.x;
    int ty = tid >> 4, tx = tid & 15;
    float acc[4][2] = {};
    for (int kk = 0; kk < Dc; kk += 32) {
        #pragma unroll
        for (int jj = 0; jj < 8; jj++) {
            int id = tid + jj * 128;
            int r = id >> 5, k = id & 31;
            sA[r][k] = g_att[(size_t)(r0 + r) * Dc + kk + k];
        }
        #pragma unroll
        for (int jj = 0; jj < 8; jj++) {
            int id = tid + jj * 128;
            int k = id >> 5, c = id & 31;
            sW[k][c] = Wo[(size_t)(kk + k) * Dc + c0 + c];
        }
        __syncthreads();
        #pragma unroll
        for (int k = 0; k < 32; k++) {
            float w0 = sW[k][tx], w1 = sW[k][tx + 16];
            #pragma unroll
            for (int i = 0; i < 4; i++) {
                float a = sA[ty * 4 + i][k];
                acc[i][0] += a * w0;
                acc[i][1] += a * w1;
            }
        }
        __syncthreads();
    }
    #pragma unroll
    for (int i = 0; i < 4; i++) {
        int row = r0 + ty * 4 + i;
        g_atto[(size_t)row * Dc + c0 + tx]      = acc[i][0] + bo[c0 + tx];
        g_atto[(size_t)row * Dc + c0 + tx + 16] = acc[i][1] + bo[c0 + tx + 16];
    }
}

// ---------------- k9: routing argmax + per-block expert counts ---------------
__global__ __launch_bounds__(64) void k9_route(const float* __restrict__ x) {
    int b = blockIdx.y;
    int n0 = blockIdx.x * 64;
    int tid = threadIdx.x;
    __shared__ float4 s_att4[Ec][DKc];   // [e][d/4], 16KB
    __shared__ float  s_red[Ec][8];
    __shared__ float  s_norm[Ec];
    __shared__ int    s_cnt[Ec];

    const float4* a4 = (const float4*)(g_atto + (size_t)b * Ec * Dc);
    for (int i = tid; i < Ec * DKc; i += 64)
        s_att4[i >> 7][i & 127] = a4[i];
    if (tid < Ec) s_cnt[tid] = 0;
    __syncthreads();

    {
        int e = tid >> 3, seg = tid & 7;
        float ps = 0.f;
        #pragma unroll
        for (int q = 0; q < 16; q++) {
            float4 v = s_att4[e][seg * 16 + q];
            ps += v.x * v.x + v.y * v.y + v.z * v.z + v.w * v.w;
        }
        s_red[e][seg] = ps;
    }
    __syncthreads();
    if (tid < Ec) {
        float s = 0.f;
        #pragma unroll
        for (int q = 0; q < 8; q++) s += s_red[tid][q];
        s_norm[tid] = sqrtf(s);
    }
    __syncthreads();

    int t = b * Nc + n0 + tid;
    const float4* xr4 = (const float4*)(x + (size_t)t * Dc);
    float acc[Ec] = {};
    #pragma unroll 4
    for (int d4 = 0; d4 < DKc; d4++) {
        float4 xv = xr4[d4];
        #pragma unroll
        for (int e = 0; e < Ec; e++) {
            float4 av = s_att4[e][d4];
            acc[e] += xv.x * av.x + xv.y * av.y + xv.z * av.z + xv.w * av.w;
        }
    }
    float best = -INFINITY; int bi = 0;
    #pragma unroll
    for (int e = 0; e < Ec; e++) {
        float v = acc[e] / s_norm[e];
        if (v > best) { best = v; bi = e; }   // first-max, matches jnp.argmax
    }
    g_idx[t] = bi;
    atomicAdd(&s_cnt[bi], 1);
    __syncthreads();
    if (tid < Ec) g_blkcnt[(b * 8 + blockIdx.x) * Ec + tid] = s_cnt[tid];
}

// ---------------- kg3: FUSED scan + scatter ----------------------------------
// Each block redundantly scans the 256x8 count table in smem (8 warps, one
// expert each), derives its own base offsets, writes g_off (identical values
// from every block), then scatters its 64 tokens.
__global__ __launch_bounds__(256) void kg3_scatter() {
    int blk = blockIdx.x;
    int tid = threadIdx.x, lane = tid & 31, w = tid >> 5;   // w = expert
    __shared__ int s_cnt[256 * Ec];     // 8KB
    __shared__ int s_myoff[Ec];         // this blk's within-expert base
    __shared__ int s_tot[Ec];
    __shared__ int s_soff[Ec];
    __shared__ int s_rank[Ec];

    #pragma unroll
    for (int jj = 0; jj < 8; jj++) s_cnt[tid + jj * 256] = g_blkcnt[tid + jj * 256];
    if (tid < Ec) s_rank[tid] = 0;
    __syncthreads();

    // warp w scans expert w across 256 blocks (8 chunks of 32)
    {
        int run = 0;
        #pragma unroll
        for (int chunk = 0; chunk < 8; chunk++) {
            int i = chunk * 32 + lane;
            int c = s_cnt[i * Ec + w];
            int s = c;
            #pragma unroll
            for (int o = 1; o < 32; o <<= 1) {
                int t = __shfl_up_sync(0xffffffffu, s, o);
                if (lane >= o) s += t;
            }
            if (i == blk) s_myoff[w] = run + s - c;   // exclusive prefix for own blk
            run += __shfl_sync(0xffffffffu, s, 31);
        }
        if (lane == 0) s_tot[w] = run;
    }
    __syncthreads();
    if (tid == 0) {
        int a = 0;
        #pragma unroll
        for (int e = 0; e < Ec; e++) { s_soff[e] = a; g_off[e] = a; a += s_tot[e]; }
        g_off[Ec] = a;
    }
    __syncthreads();

    if (tid < 64) {
        int t = blk * 64 + tid;
        int e = g_idx[t];
        int p = atomicAdd(&s_rank[e], 1);
        g_tok[s_soff[e] + s_myoff[e] + p] = t;
    }
}

// ---------------- kP1: fold conv_x into Wp -----------------------------------
__global__ __launch_bounds__(128) void kP1_fold(const float* __restrict__ Wc,
                                                const float* __restrict__ Wp) {
    int e = blockIdx.x;
    int m0 = blockIdx.y * 32;
    int tid = threadIdx.x;
    __shared__ float sWp[56][Pc];
    __shared__ float swc[Kc];
    for (int id = tid; id < 56 * Pc; id += 128) {
        int lr = id / Pc, p = id - lr * Pc;
        int l = m0 - 12 + lr;
        sWp[lr][p] = (l >= 0 && l < Dc) ? Wp[(size_t)e * Dc * Pc + (size_t)l * Pc + p] : 0.f;
    }
    if (tid < Kc) swc[tid] = Wc[e * 2 * Kc + tid];
    __syncthreads();
    if (tid < Pc) {
        #pragma unroll 2
        for (int m = 0; m < 32; m++) {
            float acc = 0.f;
            #pragma unroll
            for (int k = 0; k < Kc; k++) acc += swc[k] * sWp[m + 24 - k][tid];
            g_wx[(size_t)e * Dc * Pc + (size_t)(m0 + m) * Pc + tid] = acc;
        }
    }
}

// ---------------- kP2: z-branch per (b,e) ------------------------------------
__global__ __launch_bounds__(128) void kP2_z(const float* __restrict__ Wc,
                                             const float* __restrict__ bc,
                                             const float* __restrict__ Wp,
                                             const float* __restrict__ bp) {
    int r = blockIdx.x;      // b*8+e
    int e = r & 7;
    int tid = threadIdx.x;
    __shared__ float zp[Dc + 2 * PADc];
    __shared__ float cz[Dc];
    __shared__ float swz[Kc];
    __shared__ float s_bc;

    const float* zr = g_atto + (size_t)r * Dc;
    for (int i = tid; i < Dc + 2 * PADc; i += 128) {
        bool in = (i >= PADc) && (i < Dc + PADc);
        zp[i] = in ? zr[i - PADc] : 0.f;
    }
    if (tid < Kc) swz[tid] = Wc[e * 2 * Kc + Kc + tid];
    if (tid == 0) s_bc = bc[e];
    __syncthreads();
    #pragma unroll
    for (int jj = 0; jj < 4; jj++) {
        int l = tid * 4 + jj;
        if (l < Dc) {
            float acc = s_bc;
            #pragma unroll
            for (int k = 0; k < Kc; k++) acc += swz[k] * zp[l + k];
            cz[l] = acc;
        }
    }
    __syncthreads();
    if (tid < Pc) {
        const float* wp = Wp + (size_t)e * Dc * Pc + tid;
        float a0 = bp[e * Pc + tid], a1 = 0, a2 = 0, a3 = 0;
        for (int l = 0; l < Dc; l += 4) {
            a0 += cz[l + 0] * wp[(size_t)(l + 0) * Pc];
            a1 += cz[l + 1] * wp[(size_t)(l + 1) * Pc];
            a2 += cz[l + 2] * wp[(size_t)(l + 2) * Pc];
            a3 += cz[l + 3] * wp[(size_t)(l + 3) * Pc];
        }
        g_zlin[r * Pc + tid] = (a0 + a1) + (a2 + a3);
    }
}

// ---------------- k11: grouped GEMM  out = x @ Wxe[e] + zlin -----------------
// Champion version: 64 tokens x 96 outputs per block, 256 threads, 4x6 tile.
__global__ __launch_bounds__(256) void k11_lin(const float* __restrict__ x,
                                               float* __restrict__ out) {
    int e = blockIdx.y;
    int c = blockIdx.x;
    int off0 = g_off[e], off1 = g_off[e + 1];
    int base = off0 + c * 64;
    if (base >= off1) return;

    __shared__ float sX[64][33];     // [tok][k]
    __shared__ float sW[32][97];     // [k][p]
    __shared__ int   stok[64];
    __shared__ int   sval[64];
    int tid = threadIdx.x;
    if (tid < 64) {
        int s = base + tid;
        int v = (s < off1) ? 1 : 0;
        stok[tid] = v ? g_tok[s] : 0;
        sval[tid] = v;
    }
    __syncthreads();

    int ty = tid >> 4, tx = tid & 15;  // 16 tok-groups(4) x 16 p-lanes(6)
    float acc[4][6] = {};
    const float4* x4 = (const float4*)x;
    const float4* w4 = (const float4*)(g_wx + (size_t)e * Dc * Pc);
    for (int kk = 0; kk < Dc; kk += 32) {
        #pragma unroll
        for (int jj = 0; jj < 2; jj++) {
            int id = tid + jj * 256;
            int rr = id >> 3, k4 = id & 7;
            float4 v = sval[rr] ? x4[((size_t)stok[rr] * Dc + kk) / 4 + k4]
                                : make_float4(0.f, 0.f, 0.f, 0.f);
            sX[rr][k4 * 4 + 0] = v.x;
            sX[rr][k4 * 4 + 1] = v.y;
            sX[rr][k4 * 4 + 2] = v.z;
            sX[rr][k4 * 4 + 3] = v.w;
        }
        #pragma unroll
        for (int jj = 0; jj < 3; jj++) {
            int id = tid + jj * 256;
            int k = id / 24, p4 = id - k * 24;
            float4 v = w4[((size_t)(kk + k) * Pc) / 4 + p4];
            sW[k][p4 * 4 + 0] = v.x;
            sW[k][p4 * 4 + 1] = v.y;
            sW[k][p4 * 4 + 2] = v.z;
            sW[k][p4 * 4 + 3] = v.w;
        }
        __syncthreads();
        #pragma unroll
        for (int k = 0; k < 32; k++) {
            float w[6], a[4];
            #pragma unroll
            for (int jj = 0; jj < 6; jj++) w[jj] = sW[k][tx * 6 + jj];
            #pragma unroll
            for (int i = 0; i < 4; i++) a[i] = sX[ty * 4 + i][k];
            #pragma unroll
            for (int i = 0; i < 4; i++)
                #pragma unroll
                for (int jj = 0; jj < 6; jj++) acc[i][jj] += a[i] * w[jj];
        }
        __syncthreads();
    }
    #pragma unroll
    for (int i = 0; i < 4; i++) {
        int rr = ty * 4 + i;
        if (sval[rr]) {
            int tt = stok[rr];
            int zb = ((tt >> 9) * Ec + e) * Pc;
            #pragma unroll
            for (int jj = 0; jj < 6; jj++)
                out[(size_t)tt * Pc + tx * 6 + jj] = acc[i][jj] + g_zlin[zb + tx * 6 + jj];
        }
    }
}

// ---------------- launcher with stream-fork concurrency ----------------------
static cudaStream_t s_side = 0;
static cudaEvent_t  s_evRoot = 0, s_evP1 = 0, s_evAtto = 0, s_evP2 = 0;
static int s_init = 0;

extern "C" void kernel_launch(void* const* d_in, const int* in_sizes, int n_in,
                              void* d_out, int out_size) {
    const float* x      = (const float*)d_in[0];
    const float* router = (const float*)d_in[1];
    const float* Wq     = (const float*)d_in[2];
    const float* bq     = (const float*)d_in[3];
    const float* Wk     = (const float*)d_in[4];
    const float* bk     = (const float*)d_in[5];
    const float* Wv     = (const float*)d_in[6];
    const float* bv     = (const float*)d_in[7];
    const float* Wo     = (const float*)d_in[8];
    const float* bo     = (const float*)d_in[9];
    const float* Wc     = (const float*)d_in[10];
    const float* bc     = (const float*)d_in[11];
    const float* Wp     = (const float*)d_in[12];
    const float* bp     = (const float*)d_in[13];
    float* out = (float*)d_out;

    if (!s_init) {   // host-resource init only; launched work is identical every call
        cudaStreamCreateWithFlags(&s_side, cudaStreamNonBlocking);
        cudaEventCreateWithFlags(&s_evRoot, cudaEventDisableTiming);
        cudaEventCreateWithFlags(&s_evP1,   cudaEventDisableTiming);
        cudaEventCreateWithFlags(&s_evAtto, cudaEventDisableTiming);
        cudaEventCreateWithFlags(&s_evP2,   cudaEventDisableTiming);
        s_init = 1;
    }

    // Fork side stream from main (capture-legal: event edge)
    cudaEventRecord(s_evRoot, 0);
    cudaStreamWaitEvent(s_side, s_evRoot, 0);

    // Side stream: weight fold (no deps on attention chain)
    kP1_fold<<<dim3(Ec, 16), 128, 0, s_side>>>(Wc, Wp);
    cudaEventRecord(s_evP1, s_side);

    // Main chain
    kA_qk<<<EHc, 256>>>(router, Wq, bq, Wk, bk);
    k3_scores<<<BNc / 64, 128>>>(x);
    k4_softmax<<<Bc * EHc, 128>>>();
    k5_y<<<dim3(Dc / 64, Bc), 128>>>(x);
    k6_att<<<dim3(16, 8), 128>>>(Wv, bv);
    k7_oproj<<<dim3(16, 8), 128>>>(Wo, bo);

    // atto ready: side stream runs z-branch while main does routing
    cudaEventRecord(s_evAtto, 0);
    cudaStreamWaitEvent(s_side, s_evAtto, 0);
    kP2_z<<<Bc * Ec, 128, 0, s_side>>>(Wc, bc, Wp, bp);
    cudaEventRecord(s_evP2, s_side);

    k9_route<<<dim3(Nc / 64, Bc), 64>>>(x);
    kg3_scatter<<<256, 256>>>();

    // Join: k11 needs kP1 (g_wx), kP2 (g_zlin), kg3 (g_tok/g_off)
    cudaStreamWaitEvent(0, s_evP1, 0);
    cudaStreamWaitEvent(0, s_evP2, 0);
    k11_lin<<<dim3(BNc / 64, Ec), 256>>>(x, out);
}